// round 13
// baseline (speedup 1.0000x reference)
#include <cuda_runtime.h>
#include <cuda_fp16.h>
#include <cstdint>
#include <cmath>

// ---------------------------------------------------------------------------
// GraphSageLayer: B=4, N=4096, D_IN=128, REP=128, D_OUT=128
//
//  conv_h  : nodes, W_in/W_node/W_out, W_upd -> fp16 (one tiny streaming pass)
//  proj3h  : fp16 x fp16 ELU projections (cp.async, K=128 resident)
//  agg_both: (1 launch, z=2) fp32 adj direct; F-operand LDG->cvt at PREFETCH
//            DISTANCE 2 (held as packed fp16 regs), STS at use. R9 loop shape.
//  final16 : fp16 x fp16 tanh GEMM over upd16, K=384, 4-stage cp.async
// ---------------------------------------------------------------------------

__device__ __half g_in_rep [4l * 4096 * 128];
__device__ __half g_out_rep[4l * 4096 * 128];
__device__ __half g_upd16  [4l * 4096 * 384];   // 12 MB
__device__ __half g_nodesh [16384l * 128];      // 4 MB
__device__ __half g_Wh     [3l * 128 * 128];    // z-order: in, node, out
__device__ __half g_Wupdh  [128l * 384];

__device__ __forceinline__ uint32_t pack2(float a, float b) {
    uint32_t r;
    asm("cvt.rn.f16x2.f32 %0, %1, %2;" : "=r"(r) : "f"(b), "f"(a));
    return r;
}
__device__ __forceinline__ void cp16(uint32_t dst, const void* src) {
    asm volatile("cp.async.cg.shared.global [%0], [%1], 16;" :: "r"(dst), "l"(src));
}
__device__ __forceinline__ void cp_commit() {
    asm volatile("cp.async.commit_group;");
}
__device__ __forceinline__ void cp_wait2() {
    asm volatile("cp.async.wait_group 2;");
}
__device__ __forceinline__ void cp_wait0() {
    asm volatile("cp.async.wait_group 0;");
}
__device__ __forceinline__ void ldsm4(uint32_t* r, uint32_t a) {
    asm volatile("ldmatrix.sync.aligned.m8n8.x4.shared.b16 {%0,%1,%2,%3}, [%4];"
        : "=r"(r[0]), "=r"(r[1]), "=r"(r[2]), "=r"(r[3]) : "r"(a));
}
__device__ __forceinline__ void ldsm4t(uint32_t* r, uint32_t a) {
    asm volatile("ldmatrix.sync.aligned.m8n8.x4.trans.shared.b16 {%0,%1,%2,%3}, [%4];"
        : "=r"(r[0]), "=r"(r[1]), "=r"(r[2]), "=r"(r[3]) : "r"(a));
}
__device__ __forceinline__ void mma16816(float* c, const uint32_t* a,
                                         uint32_t b0, uint32_t b1) {
    asm volatile(
        "mma.sync.aligned.m16n8k16.row.col.f32.f16.f16.f32 "
        "{%0,%1,%2,%3}, {%4,%5,%6,%7}, {%8,%9}, {%0,%1,%2,%3};\n"
        : "+f"(c[0]), "+f"(c[1]), "+f"(c[2]), "+f"(c[3])
        : "r"(a[0]), "r"(a[1]), "r"(a[2]), "r"(a[3]), "r"(b0), "r"(b1));
}

// ===========================================================================
// conv_h: fp32 -> fp16 for nodes + all weight matrices. 8 elems/thread.
// ===========================================================================
__global__ __launch_bounds__(256)
void conv_h(const float* __restrict__ nodes,
            const float* __restrict__ W_in, const float* __restrict__ W_node,
            const float* __restrict__ W_out, const float* __restrict__ W_upd,
            __half* __restrict__ nodesh, __half* __restrict__ Wh,
            __half* __restrict__ Wupdh)
{
    const int bx = blockIdx.x;
    const float* src; __half* dst; long g;
    if (bx < 1024)      { src = nodes;  dst = nodesh;     g = (long)bx * 256 + threadIdx.x; }
    else if (bx < 1032) { src = W_in;   dst = Wh;         g = (long)(bx - 1024) * 256 + threadIdx.x; }
    else if (bx < 1040) { src = W_node; dst = Wh + 16384; g = (long)(bx - 1032) * 256 + threadIdx.x; }
    else if (bx < 1048) { src = W_out;  dst = Wh + 32768; g = (long)(bx - 1040) * 256 + threadIdx.x; }
    else                { src = W_upd;  dst = Wupdh;      g = (long)(bx - 1048) * 256 + threadIdx.x; }
    float4 a = __ldcs((const float4*)src + 2 * g);
    float4 b = __ldcs((const float4*)src + 2 * g + 1);
    ((uint4*)dst)[g] = make_uint4(pack2(a.x, a.y), pack2(a.z, a.w),
                                  pack2(b.x, b.y), pack2(b.z, b.w));
}

// ===========================================================================
// proj3h: grid (256,1,3), 256 thr. CTA 64x128, K=128 fully resident fp16.
// ===========================================================================
__global__ __launch_bounds__(256, 2)
void proj3h(const __half* __restrict__ nodesh, const __half* __restrict__ Wh,
            const float* __restrict__ b_in, const float* __restrict__ b_node,
            const float* __restrict__ b_out,
            __half* __restrict__ in_rep, __half* __restrict__ out_rep,
            __half* __restrict__ upd16)
{
    extern __shared__ char sm[];
    const int tid  = threadIdx.x;
    const int lane = tid & 31;
    const int warp = tid >> 5;
    const int wm = warp >> 2, wn = warp & 3;
    const int g = lane >> 2, t = lane & 3;
    const int m0 = blockIdx.x * 64;
    const int z  = blockIdx.z;

    const __half* Wz  = Wh + z * 16384;
    const float* bias = (z == 0) ? b_in : (z == 1) ? b_node : b_out;

    const uint32_t sA = (uint32_t)__cvta_generic_to_shared(sm);
    const uint32_t sB = sA + 17408;

    #pragma unroll
    for (int i = 0; i < 4; i++) {
        const int c = i * 256 + tid, row = c >> 4, ch = c & 15;
        cp16(sA + row * 272 + ch * 16, nodesh + (long)(m0 + row) * 128 + ch * 8);
    }
    #pragma unroll
    for (int i = 0; i < 8; i++) {
        const int c = i * 256 + tid, row = c >> 4, ch = c & 15;
        cp16(sB + row * 272 + ch * 16, Wz + (long)row * 128 + ch * 8);
    }
    cp_commit();
    cp_wait0();
    __syncthreads();

    float acc[2][4][4];
    #pragma unroll
    for (int i = 0; i < 2; i++)
        #pragma unroll
        for (int j = 0; j < 4; j++)
            #pragma unroll
            for (int l = 0; l < 4; l++) acc[i][j][l] = 0.f;

    #pragma unroll
    for (int k = 0; k < 8; k++) {
        const uint32_t kOff = ((lane >> 4) + 2 * k) * 16;
        uint32_t aF[2][4], bR[2][4];
        #pragma unroll
        for (int mt = 0; mt < 2; mt++)
            ldsm4(aF[mt], sA + (wm * 32 + mt * 16 + (lane & 15)) * 272 + kOff);
        #pragma unroll
        for (int i = 0; i < 2; i++)
            ldsm4(bR[i], sB + (wn * 32 + i * 16 + (lane & 15)) * 272 + kOff);
        #pragma unroll
        for (int mt = 0; mt < 2; mt++)
            #pragma unroll
            for (int nt = 0; nt < 4; nt++)
                mma16816(acc[mt][nt], aF[mt],
                         bR[nt >> 1][nt & 1], bR[nt >> 1][(nt & 1) + 2]);
    }

    #pragma unroll
    for (int mt = 0; mt < 2; mt++)
        #pragma unroll
        for (int nt = 0; nt < 4; nt++) {
            const int row = m0 + wm * 32 + mt * 16 + g;
            const int col = wn * 32 + nt * 8 + 2 * t;
            const float b0 = __ldg(bias + col), b1 = __ldg(bias + col + 1);
            float x0 = acc[mt][nt][0] + b0, x1 = acc[mt][nt][1] + b1;
            float x2 = acc[mt][nt][2] + b0, x3 = acc[mt][nt][3] + b1;
            x0 = x0 > 0.f ? x0 : expm1f(x0);
            x1 = x1 > 0.f ? x1 : expm1f(x1);
            x2 = x2 > 0.f ? x2 : expm1f(x2);
            x3 = x3 > 0.f ? x3 : expm1f(x3);
            if (z == 1) {
                *(uint32_t*)&upd16[(long)row       * 384 + 128 + col] = pack2(x0, x1);
                *(uint32_t*)&upd16[(long)(row + 8) * 384 + 128 + col] = pack2(x2, x3);
            } else {
                __half* D = (z == 0) ? in_rep : out_rep;
                *(uint32_t*)&D[(long)row       * 128 + col] = pack2(x0, x1);
                *(uint32_t*)&D[(long)(row + 8) * 128 + col] = pack2(x2, x3);
            }
        }
}

// ===========================================================================
// Aggregation: CTA 128x128, BK=32. R9 loop shape; ONLY change vs R12:
// F-operand prefetch distance 2, held as packed fp16 regs (fvh[2][8], 16 regs
// total — same footprint as the old fv[4] fp32 tile).
// ===========================================================================
template<bool OUTT>
__device__ __forceinline__ void agg_body(
    const float* __restrict__ adj, const __half* __restrict__ rep,
    __half* __restrict__ upd, char* smem)
{
    const int tid  = threadIdx.x;
    const int lane = tid & 31;
    const int warp = tid >> 5;
    const int wm   = warp >> 2;
    const int wn   = warp & 3;
    const int g    = lane >> 2;
    const int t    = lane & 3;
    const int tile0 = blockIdx.x * 128;
    const long b   = blockIdx.y;

    const float*  adjB = adj + b * (4096l * 4096);
    const __half* repB = rep + b * (4096l * 128);
    __half*       updB = upd + b * (4096l * 384);

    const uint32_t smBase = (uint32_t)__cvta_generic_to_shared(smem);
    const uint32_t sF0 = OUTT ? (smBase + 34816) : smBase;
    const int      FSTRIDE = OUTT ? 8704 : 10240;
    const uint32_t sR0 = OUTT ? smBase : (smBase + 20480);

    float acc[4][4][4];
    #pragma unroll
    for (int i = 0; i < 4; i++)
        #pragma unroll
        for (int j = 0; j < 4; j++)
            #pragma unroll
            for (int l = 0; l < 4; l++) acc[i][j][l] = 0.f;

    const int f_row = OUTT ? (tid >> 3) : (tid >> 1);
    const int f_ch  = OUTT ? (tid & 7)  : (tid & 1);
    const float* fSrcBase = OUTT
        ? (adjB + (long)f_row * 4096 + tile0 + f_ch * 16)
        : (adjB + (long)(tile0 + f_row) * 4096 + f_ch * 16);
    const uint32_t fDst = (OUTT ? f_row * 272 : f_row * 80) + f_ch * 32;

    // prefetch-distance-2: load 16 fp32, convert immediately, keep 8 packed regs
    uint32_t fvh[2][8];
    auto ldcvtF = [&](int k0, int s) {
        const float* p = OUTT ? (fSrcBase + (long)k0 * 4096) : (fSrcBase + k0);
        #pragma unroll
        for (int i = 0; i < 4; i++) {
            float4 v = ((const float4*)p)[i];
            fvh[s][2 * i]     = pack2(v.x * 4096.f, v.y * 4096.f);
            fvh[s][2 * i + 1] = pack2(v.z * 4096.f, v.w * 4096.f);
        }
    };
    auto stsF = [&](int buf, int s) {
        const uint32_t d = (sF0 - smBase) + buf * FSTRIDE + fDst;
        *(uint4*)(smem + d)      = make_uint4(fvh[s][0], fvh[s][1], fvh[s][2], fvh[s][3]);
        *(uint4*)(smem + d + 16) = make_uint4(fvh[s][4], fvh[s][5], fvh[s][6], fvh[s][7]);
    };

    const int r_k  = tid >> 4;
    const int r_nc = tid & 15;
    auto cpR = [&](int st, int k0) {
        const uint32_t sR = sR0 + st * 8704;
        cp16(sR + r_k * 272 + r_nc * 16,        repB + (long)(k0 + r_k) * 128 + r_nc * 8);
        cp16(sR + (r_k + 16) * 272 + r_nc * 16, repB + (long)(k0 + r_k + 16) * 128 + r_nc * 8);
    };

    auto compute = [&](int kt) {
        const uint32_t sA = OUTT ? (sR0 + (kt & 3) * 8704) : (sF0 + (kt & 1) * FSTRIDE);
        const uint32_t sB = OUTT ? (sF0 + (kt & 1) * FSTRIDE) : (sR0 + (kt & 3) * 8704);
        #pragma unroll
        for (int ks = 0; ks < 2; ks++) {
            uint32_t aF[4][4], bF[2][4];
            #pragma unroll
            for (int mt = 0; mt < 4; mt++) {
                if (!OUTT) {
                    ldsm4(aF[mt], sA + (wm * 64 + mt * 16 + (lane & 15)) * 80
                                     + ((lane >> 4) + 2 * ks) * 16);
                } else {
                    ldsm4t(aF[mt], sA + ((lane & 7) + (lane >> 4) * 8 + 16 * ks) * 272
                                      + (wm * 64 + mt * 16 + ((lane >> 3) & 1) * 8) * 2);
                }
            }
            #pragma unroll
            for (int nt = 0; nt < 2; nt++)
                ldsm4t(bF[nt], sB + ((lane & 15) + 16 * ks) * 272
                                  + wn * 64 + nt * 32 + (lane >> 4) * 16);
            #pragma unroll
            for (int mt = 0; mt < 4; mt++)
                #pragma unroll
                for (int n8 = 0; n8 < 4; n8++)
                    mma16816(acc[mt][n8], aF[mt],
                             bF[n8 >> 1][(n8 & 1) * 2], bF[n8 >> 1][(n8 & 1) * 2 + 1]);
        }
    };

    // prologue: F tiles 0 and 1 in regs; R 3 stages in flight
    ldcvtF(0, 0);
    ldcvtF(32, 1);
    #pragma unroll
    for (int s = 0; s < 3; s++) { cpR(s, s * 32); cp_commit(); }

    #pragma unroll 1
    for (int kt = 0; kt < 128; kt++) {
        stsF(kt & 1, kt & 1);                      // consume reg tile kt
        cp_wait2();
        __syncthreads();
        if (kt + 2 < 128) ldcvtF((kt + 2) * 32, kt & 1);   // refill for kt+2
        const int nx = kt + 3;
        if (nx < 128) cpR(nx & 3, nx * 32);
        cp_commit();
        compute(kt);
    }

    const float s = 1.f / 4096.f;
    if (!OUTT) {
        #pragma unroll
        for (int mt = 0; mt < 4; mt++)
            #pragma unroll
            for (int n8 = 0; n8 < 4; n8++) {
                const int row = tile0 + wm * 64 + mt * 16 + g;
                const int col = wn * 32 + n8 * 8 + 2 * t;
                *(uint32_t*)&updB[(long)row * 384 + col] =
                    pack2(acc[mt][n8][0] * s, acc[mt][n8][1] * s);
                *(uint32_t*)&updB[(long)(row + 8) * 384 + col] =
                    pack2(acc[mt][n8][2] * s, acc[mt][n8][3] * s);
            }
    } else {
        __syncthreads();
        float* fsm = (float*)smem;   // [v][132] = 67584 B
        #pragma unroll
        for (int mt = 0; mt < 4; mt++)
            #pragma unroll
            for (int n8 = 0; n8 < 4; n8++) {
                const int v = wm * 64 + mt * 16 + g;
                const int j = wn * 32 + n8 * 8 + 2 * t;
                fsm[v * 132 + j]           = acc[mt][n8][0] * s;
                fsm[v * 132 + j + 1]       = acc[mt][n8][1] * s;
                fsm[(v + 8) * 132 + j]     = acc[mt][n8][2] * s;
                fsm[(v + 8) * 132 + j + 1] = acc[mt][n8][3] * s;
            }
        __syncthreads();
        const int j  = tid >> 1;
        const int vb = (tid & 1) * 64;
        __half* dst = &updB[(long)(tile0 + j) * 384 + 256 + vb];
        #pragma unroll
        for (int i = 0; i < 16; i++) {
            const int v = vb + i * 4;
            *(uint2*)(dst + i * 4) = make_uint2(
                pack2(fsm[v * 132 + j],       fsm[(v + 1) * 132 + j]),
                pack2(fsm[(v + 2) * 132 + j], fsm[(v + 3) * 132 + j]));
        }
    }
}

__global__ __launch_bounds__(256, 2)
void agg_both(const float* __restrict__ adj,
              const __half* __restrict__ in_rep,
              const __half* __restrict__ out_rep,
              __half* __restrict__ upd16)
{
    extern __shared__ char smem[];
    if (blockIdx.z == 0) agg_body<false>(adj, in_rep,  upd16, smem);
    else                 agg_body<true >(adj, out_rep, upd16, smem);
}

// ===========================================================================
// final16: grid 256, CTA 64x128, K=384, 4-stage cp.async fp16 both operands.
// ===========================================================================
__global__ __launch_bounds__(256, 2)
void final16(const __half* __restrict__ upd16, const __half* __restrict__ Wupdh,
             const float* __restrict__ bias, float* __restrict__ out)
{
    extern __shared__ char sm[];
    const int tid  = threadIdx.x;
    const int lane = tid & 31;
    const int warp = tid >> 5;
    const int wm = warp >> 2, wn = warp & 3;
    const int g = lane >> 2, t = lane & 3;
    const int m0 = blockIdx.x * 64;

    const uint32_t smBase = (uint32_t)__cvta_generic_to_shared(sm);

    float acc[2][4][4];
    #pragma unroll
    for (int i = 0; i < 2; i++)
        #pragma unroll
        for (int j = 0; j < 4; j++)
            #pragma unroll
            for (int l = 0; l < 4; l++) acc[i][j][l] = 0.f;

    auto cpStage = [&](int st, int k0) {
        const uint32_t sA = smBase + st * 15360;
        const uint32_t sB = sA + 5120;
        {
            const int row = tid >> 2, ch = tid & 3;
            cp16(sA + row * 80 + ch * 16, upd16 + (long)(m0 + row) * 384 + k0 + ch * 8);
        }
        #pragma unroll
        for (int i = 0; i < 2; i++) {
            const int c = i * 256 + tid, row = c >> 2, ch = c & 3;
            cp16(sB + row * 80 + ch * 16, Wupdh + (long)row * 384 + k0 + ch * 8);
        }
    };

    auto compute = [&](int st) {
        const uint32_t sA = smBase + st * 15360;
        const uint32_t sB = sA + 5120;
        #pragma unroll
        for (int ks = 0; ks < 2; ks++) {
            const uint32_t kOff = ((lane >> 4) + 2 * ks) * 16;
            uint32_t aF[2][4], bR[2][4];
            #pragma unroll
            for (int mt = 0; mt < 2; mt++)
                ldsm4(aF[mt], sA + (wm * 32 + mt * 16 + (lane & 15)) * 80 + kOff);
            #pragma unroll
            for (int i = 0; i < 2; i++)
                ldsm4(bR[i], sB + (wn * 32 + i * 16 + (lane & 15)) * 80 + kOff);
            #pragma unroll
            for (int mt = 0; mt < 2; mt++)
                #pragma unroll
                for (int nt = 0; nt < 4; nt++)
                    mma16816(acc[mt][nt], aF[mt],
                             bR[nt >> 1][nt & 1], bR[nt >> 1][(nt & 1) + 2]);
        }
    };

    #pragma unroll
    for (int s = 0; s < 3; s++) { cpStage(s, s * 32); cp_commit(); }

    #pragma unroll 1
    for (int kt = 0; kt < 12; kt++) {
        cp_wait2();
        __syncthreads();
        const int nx = kt + 3;
        if (nx < 12) cpStage(nx & 3, nx * 32);
        cp_commit();
        compute(kt & 3);
    }

    #pragma unroll
    for (int mt = 0; mt < 2; mt++)
        #pragma unroll
        for (int nt = 0; nt < 4; nt++) {
            const int row = m0 + wm * 32 + mt * 16 + g;
            const int col = wn * 32 + nt * 8 + 2 * t;
            const float b0 = __ldg(bias + col), b1 = __ldg(bias + col + 1);
            float x0 = tanhf(acc[mt][nt][0] + b0), x1 = tanhf(acc[mt][nt][1] + b1);
            float x2 = tanhf(acc[mt][nt][2] + b0), x3 = tanhf(acc[mt][nt][3] + b1);
            *(float2*)&out[(long)row       * 128 + col] = make_float2(x0, x1);
            *(float2*)&out[(long)(row + 8) * 128 + col] = make_float2(x2, x3);
        }
}

// ===========================================================================
extern "C" void kernel_launch(void* const* d_in, const int* in_sizes, int n_in,
                              void* d_out, int out_size)
{
    const float* nodes  = (const float*)d_in[0];
    const float* adj    = (const float*)d_in[1];
    const float* W_in   = (const float*)d_in[2];
    const float* b_in   = (const float*)d_in[3];
    const float* W_out  = (const float*)d_in[4];
    const float* b_out  = (const float*)d_in[5];
    const float* W_node = (const float*)d_in[6];
    const float* b_node = (const float*)d_in[7];
    const float* W_upd  = (const float*)d_in[8];
    const float* b_upd  = (const float*)d_in[9];
    float* out = (float*)d_out;

    __half *in_rep, *out_rep, *upd16, *nodesh, *Wh, *Wupdh;
    cudaGetSymbolAddress((void**)&in_rep,  g_in_rep);
    cudaGetSymbolAddress((void**)&out_rep, g_out_rep);
    cudaGetSymbolAddress((void**)&upd16,   g_upd16);
    cudaGetSymbolAddress((void**)&nodesh,  g_nodesh);
    cudaGetSymbolAddress((void**)&Wh,      g_Wh);
    cudaGetSymbolAddress((void**)&Wupdh,   g_Wupdh);

    const int SMEM_PROJ  = 52224;
    const int SMEM_AGG   = 128 * 132 * 4;  // 67584
    const int SMEM_FINAL = 61440;
    cudaFuncSetAttribute(proj3h,
                         cudaFuncAttributeMaxDynamicSharedMemorySize, SMEM_PROJ);
    cudaFuncSetAttribute(agg_both,
                         cudaFuncAttributeMaxDynamicSharedMemorySize, SMEM_AGG);
    cudaFuncSetAttribute(final16,
                         cudaFuncAttributeMaxDynamicSharedMemorySize, SMEM_FINAL);

    // 0) one-shot fp16 conversion of nodes + all weights
    conv_h<<<1072, 256>>>(nodes, W_in, W_node, W_out, W_upd, nodesh, Wh, Wupdh);

    // 1) three ELU projections (all-fp16 operands)
    proj3h<<<dim3(256, 1, 3), 256, SMEM_PROJ>>>(nodesh, Wh, b_in, b_node, b_out,
                                                in_rep, out_rep, upd16);

    // 2+3) both aggregations (fp32 adj direct; distance-2 F prefetch)
    agg_both<<<dim3(32, 4, 2), 256, SMEM_AGG>>>(adj, in_rep, out_rep, upd16);

    // 4) out = tanh(upd @ W_upd^T + b_upd)  (all-fp16 operands)
    final16<<<256, 256, SMEM_FINAL>>>(upd16, Wupdh, b_upd, out);
}

// round 14
// speedup vs baseline: 1.3761x; 1.3761x over previous
#include <cuda_runtime.h>
#include <cuda_fp16.h>
#include <cstdint>
#include <cmath>

// ---------------------------------------------------------------------------
// GraphSageLayer: B=4, N=4096, D_IN=128, REP=128, D_OUT=128
//
//  conv_h  : nodes, W_in/W_node/W_out, W_upd -> fp16 (one tiny streaming pass)
//  proj3h  : fp16 x fp16 ELU projections (cp.async, K=128 resident)
//  agg_both: (1 launch, z=2) fp32 adj direct (__ldcs streaming), cvt at STS
//            (R12 loop, prefetch distance 1), epilogues write upd16 fp16
//  final16 : fp16 x fp16 tanh GEMM over upd16, K=384, 4-stage cp.async
// ---------------------------------------------------------------------------

__device__ __half g_in_rep [4l * 4096 * 128];
__device__ __half g_out_rep[4l * 4096 * 128];
__device__ __half g_upd16  [4l * 4096 * 384];   // 12 MB
__device__ __half g_nodesh [16384l * 128];      // 4 MB
__device__ __half g_Wh     [3l * 128 * 128];    // z-order: in, node, out
__device__ __half g_Wupdh  [128l * 384];

__device__ __forceinline__ uint32_t pack2(float a, float b) {
    uint32_t r;
    asm("cvt.rn.f16x2.f32 %0, %1, %2;" : "=r"(r) : "f"(b), "f"(a));
    return r;
}
__device__ __forceinline__ void cp16(uint32_t dst, const void* src) {
    asm volatile("cp.async.cg.shared.global [%0], [%1], 16;" :: "r"(dst), "l"(src));
}
__device__ __forceinline__ void cp_commit() {
    asm volatile("cp.async.commit_group;");
}
__device__ __forceinline__ void cp_wait2() {
    asm volatile("cp.async.wait_group 2;");
}
__device__ __forceinline__ void cp_wait0() {
    asm volatile("cp.async.wait_group 0;");
}
__device__ __forceinline__ void ldsm4(uint32_t* r, uint32_t a) {
    asm volatile("ldmatrix.sync.aligned.m8n8.x4.shared.b16 {%0,%1,%2,%3}, [%4];"
        : "=r"(r[0]), "=r"(r[1]), "=r"(r[2]), "=r"(r[3]) : "r"(a));
}
__device__ __forceinline__ void ldsm4t(uint32_t* r, uint32_t a) {
    asm volatile("ldmatrix.sync.aligned.m8n8.x4.trans.shared.b16 {%0,%1,%2,%3}, [%4];"
        : "=r"(r[0]), "=r"(r[1]), "=r"(r[2]), "=r"(r[3]) : "r"(a));
}
__device__ __forceinline__ void mma16816(float* c, const uint32_t* a,
                                         uint32_t b0, uint32_t b1) {
    asm volatile(
        "mma.sync.aligned.m16n8k16.row.col.f32.f16.f16.f32 "
        "{%0,%1,%2,%3}, {%4,%5,%6,%7}, {%8,%9}, {%0,%1,%2,%3};\n"
        : "+f"(c[0]), "+f"(c[1]), "+f"(c[2]), "+f"(c[3])
        : "r"(a[0]), "r"(a[1]), "r"(a[2]), "r"(a[3]), "r"(b0), "r"(b1));
}

// ===========================================================================
// conv_h: fp32 -> fp16 for nodes + all weight matrices. 8 elems/thread.
// ===========================================================================
__global__ __launch_bounds__(256)
void conv_h(const float* __restrict__ nodes,
            const float* __restrict__ W_in, const float* __restrict__ W_node,
            const float* __restrict__ W_out, const float* __restrict__ W_upd,
            __half* __restrict__ nodesh, __half* __restrict__ Wh,
            __half* __restrict__ Wupdh)
{
    const int bx = blockIdx.x;
    const float* src; __half* dst; long g;
    if (bx < 1024)      { src = nodes;  dst = nodesh;     g = (long)bx * 256 + threadIdx.x; }
    else if (bx < 1032) { src = W_in;   dst = Wh;         g = (long)(bx - 1024) * 256 + threadIdx.x; }
    else if (bx < 1040) { src = W_node; dst = Wh + 16384; g = (long)(bx - 1032) * 256 + threadIdx.x; }
    else if (bx < 1048) { src = W_out;  dst = Wh + 32768; g = (long)(bx - 1040) * 256 + threadIdx.x; }
    else                { src = W_upd;  dst = Wupdh;      g = (long)(bx - 1048) * 256 + threadIdx.x; }
    float4 a = __ldcs((const float4*)src + 2 * g);
    float4 b = __ldcs((const float4*)src + 2 * g + 1);
    ((uint4*)dst)[g] = make_uint4(pack2(a.x, a.y), pack2(a.z, a.w),
                                  pack2(b.x, b.y), pack2(b.z, b.w));
}

// ===========================================================================
// proj3h: grid (256,1,3), 256 thr. CTA 64x128, K=128 fully resident fp16.
// ===========================================================================
__global__ __launch_bounds__(256, 2)
void proj3h(const __half* __restrict__ nodesh, const __half* __restrict__ Wh,
            const float* __restrict__ b_in, const float* __restrict__ b_node,
            const float* __restrict__ b_out,
            __half* __restrict__ in_rep, __half* __restrict__ out_rep,
            __half* __restrict__ upd16)
{
    extern __shared__ char sm[];
    const int tid  = threadIdx.x;
    const int lane = tid & 31;
    const int warp = tid >> 5;
    const int wm = warp >> 2, wn = warp & 3;
    const int g = lane >> 2, t = lane & 3;
    const int m0 = blockIdx.x * 64;
    const int z  = blockIdx.z;

    const __half* Wz  = Wh + z * 16384;
    const float* bias = (z == 0) ? b_in : (z == 1) ? b_node : b_out;

    const uint32_t sA = (uint32_t)__cvta_generic_to_shared(sm);
    const uint32_t sB = sA + 17408;

    #pragma unroll
    for (int i = 0; i < 4; i++) {
        const int c = i * 256 + tid, row = c >> 4, ch = c & 15;
        cp16(sA + row * 272 + ch * 16, nodesh + (long)(m0 + row) * 128 + ch * 8);
    }
    #pragma unroll
    for (int i = 0; i < 8; i++) {
        const int c = i * 256 + tid, row = c >> 4, ch = c & 15;
        cp16(sB + row * 272 + ch * 16, Wz + (long)row * 128 + ch * 8);
    }
    cp_commit();
    cp_wait0();
    __syncthreads();

    float acc[2][4][4];
    #pragma unroll
    for (int i = 0; i < 2; i++)
        #pragma unroll
        for (int j = 0; j < 4; j++)
            #pragma unroll
            for (int l = 0; l < 4; l++) acc[i][j][l] = 0.f;

    #pragma unroll
    for (int k = 0; k < 8; k++) {
        const uint32_t kOff = ((lane >> 4) + 2 * k) * 16;
        uint32_t aF[2][4], bR[2][4];
        #pragma unroll
        for (int mt = 0; mt < 2; mt++)
            ldsm4(aF[mt], sA + (wm * 32 + mt * 16 + (lane & 15)) * 272 + kOff);
        #pragma unroll
        for (int i = 0; i < 2; i++)
            ldsm4(bR[i], sB + (wn * 32 + i * 16 + (lane & 15)) * 272 + kOff);
        #pragma unroll
        for (int mt = 0; mt < 2; mt++)
            #pragma unroll
            for (int nt = 0; nt < 4; nt++)
                mma16816(acc[mt][nt], aF[mt],
                         bR[nt >> 1][nt & 1], bR[nt >> 1][(nt & 1) + 2]);
    }

    #pragma unroll
    for (int mt = 0; mt < 2; mt++)
        #pragma unroll
        for (int nt = 0; nt < 4; nt++) {
            const int row = m0 + wm * 32 + mt * 16 + g;
            const int col = wn * 32 + nt * 8 + 2 * t;
            const float b0 = __ldg(bias + col), b1 = __ldg(bias + col + 1);
            float x0 = acc[mt][nt][0] + b0, x1 = acc[mt][nt][1] + b1;
            float x2 = acc[mt][nt][2] + b0, x3 = acc[mt][nt][3] + b1;
            x0 = x0 > 0.f ? x0 : expm1f(x0);
            x1 = x1 > 0.f ? x1 : expm1f(x1);
            x2 = x2 > 0.f ? x2 : expm1f(x2);
            x3 = x3 > 0.f ? x3 : expm1f(x3);
            if (z == 1) {
                *(uint32_t*)&upd16[(long)row       * 384 + 128 + col] = pack2(x0, x1);
                *(uint32_t*)&upd16[(long)(row + 8) * 384 + 128 + col] = pack2(x2, x3);
            } else {
                __half* D = (z == 0) ? in_rep : out_rep;
                *(uint32_t*)&D[(long)row       * 128 + col] = pack2(x0, x1);
                *(uint32_t*)&D[(long)(row + 8) * 128 + col] = pack2(x2, x3);
            }
        }
}

// ===========================================================================
// Aggregation (EXACT R12 loop; only change: __ldcs on adj LDG): CTA 128x128,
// BK=32. adj: fp32 LDG(streaming) -> cvt(x4096) at STS time, 2 smem bufs,
// reg-prefetch distance 1. rep: fp16 cp.async, 4-stage.
// ===========================================================================
template<bool OUTT>
__device__ __forceinline__ void agg_body(
    const float* __restrict__ adj, const __half* __restrict__ rep,
    __half* __restrict__ upd, char* smem)
{
    const int tid  = threadIdx.x;
    const int lane = tid & 31;
    const int warp = tid >> 5;
    const int wm   = warp >> 2;
    const int wn   = warp & 3;
    const int g    = lane >> 2;
    const int t    = lane & 3;
    const int tile0 = blockIdx.x * 128;
    const long b   = blockIdx.y;

    const float*  adjB = adj + b * (4096l * 4096);
    const __half* repB = rep + b * (4096l * 128);
    __half*       updB = upd + b * (4096l * 384);

    const uint32_t smBase = (uint32_t)__cvta_generic_to_shared(smem);
    const uint32_t sF0 = OUTT ? (smBase + 34816) : smBase;
    const int      FSTRIDE = OUTT ? 8704 : 10240;
    const uint32_t sR0 = OUTT ? smBase : (smBase + 20480);

    float acc[4][4][4];
    #pragma unroll
    for (int i = 0; i < 4; i++)
        #pragma unroll
        for (int j = 0; j < 4; j++)
            #pragma unroll
            for (int l = 0; l < 4; l++) acc[i][j][l] = 0.f;

    const int f_row = OUTT ? (tid >> 3) : (tid >> 1);
    const int f_ch  = OUTT ? (tid & 7)  : (tid & 1);
    const float* fSrcBase = OUTT
        ? (adjB + (long)f_row * 4096 + tile0 + f_ch * 16)
        : (adjB + (long)(tile0 + f_row) * 4096 + f_ch * 16);
    const uint32_t fDst = (OUTT ? f_row * 272 : f_row * 80) + f_ch * 32;

    float4 fv[4];
    auto ldF = [&](int k0) {
        const float* p = OUTT ? (fSrcBase + (long)k0 * 4096) : (fSrcBase + k0);
        #pragma unroll
        for (int i = 0; i < 4; i++) fv[i] = __ldcs((const float4*)p + i);
    };
    auto stsF = [&](int buf) {
        uint32_t w[8];
        #pragma unroll
        for (int i = 0; i < 4; i++) {
            w[2 * i]     = pack2(fv[i].x * 4096.f, fv[i].y * 4096.f);
            w[2 * i + 1] = pack2(fv[i].z * 4096.f, fv[i].w * 4096.f);
        }
        const uint32_t d = (sF0 - smBase) + buf * FSTRIDE + fDst;
        *(uint4*)(smem + d)      = make_uint4(w[0], w[1], w[2], w[3]);
        *(uint4*)(smem + d + 16) = make_uint4(w[4], w[5], w[6], w[7]);
    };

    const int r_k  = tid >> 4;
    const int r_nc = tid & 15;
    auto cpR = [&](int st, int k0) {
        const uint32_t sR = sR0 + st * 8704;
        cp16(sR + r_k * 272 + r_nc * 16,        repB + (long)(k0 + r_k) * 128 + r_nc * 8);
        cp16(sR + (r_k + 16) * 272 + r_nc * 16, repB + (long)(k0 + r_k + 16) * 128 + r_nc * 8);
    };

    auto compute = [&](int kt) {
        const uint32_t sA = OUTT ? (sR0 + (kt & 3) * 8704) : (sF0 + (kt & 1) * FSTRIDE);
        const uint32_t sB = OUTT ? (sF0 + (kt & 1) * FSTRIDE) : (sR0 + (kt & 3) * 8704);
        #pragma unroll
        for (int ks = 0; ks < 2; ks++) {
            uint32_t aF[4][4], bF[2][4];
            #pragma unroll
            for (int mt = 0; mt < 4; mt++) {
                if (!OUTT) {
                    ldsm4(aF[mt], sA + (wm * 64 + mt * 16 + (lane & 15)) * 80
                                     + ((lane >> 4) + 2 * ks) * 16);
                } else {
                    ldsm4t(aF[mt], sA + ((lane & 7) + (lane >> 4) * 8 + 16 * ks) * 272
                                      + (wm * 64 + mt * 16 + ((lane >> 3) & 1) * 8) * 2);
                }
            }
            #pragma unroll
            for (int nt = 0; nt < 2; nt++)
                ldsm4t(bF[nt], sB + ((lane & 15) + 16 * ks) * 272
                                  + wn * 64 + nt * 32 + (lane >> 4) * 16);
            #pragma unroll
            for (int mt = 0; mt < 4; mt++)
                #pragma unroll
                for (int n8 = 0; n8 < 4; n8++)
                    mma16816(acc[mt][n8], aF[mt],
                             bF[n8 >> 1][(n8 & 1) * 2], bF[n8 >> 1][(n8 & 1) * 2 + 1]);
        }
    };

    // prologue
    ldF(0);
    #pragma unroll
    for (int s = 0; s < 3; s++) { cpR(s, s * 32); cp_commit(); }

    #pragma unroll 1
    for (int kt = 0; kt < 128; kt++) {
        stsF(kt & 1);
        cp_wait2();
        __syncthreads();
        if (kt + 1 < 128) ldF((kt + 1) * 32);
        const int nx = kt + 3;
        if (nx < 128) cpR(nx & 3, nx * 32);
        cp_commit();
        compute(kt);
    }

    const float s = 1.f / 4096.f;
    if (!OUTT) {
        #pragma unroll
        for (int mt = 0; mt < 4; mt++)
            #pragma unroll
            for (int n8 = 0; n8 < 4; n8++) {
                const int row = tile0 + wm * 64 + mt * 16 + g;
                const int col = wn * 32 + n8 * 8 + 2 * t;
                *(uint32_t*)&updB[(long)row * 384 + col] =
                    pack2(acc[mt][n8][0] * s, acc[mt][n8][1] * s);
                *(uint32_t*)&updB[(long)(row + 8) * 384 + col] =
                    pack2(acc[mt][n8][2] * s, acc[mt][n8][3] * s);
            }
    } else {
        __syncthreads();
        float* fsm = (float*)smem;   // [v][132] = 67584 B
        #pragma unroll
        for (int mt = 0; mt < 4; mt++)
            #pragma unroll
            for (int n8 = 0; n8 < 4; n8++) {
                const int v = wm * 64 + mt * 16 + g;
                const int j = wn * 32 + n8 * 8 + 2 * t;
                fsm[v * 132 + j]           = acc[mt][n8][0] * s;
                fsm[v * 132 + j + 1]       = acc[mt][n8][1] * s;
                fsm[(v + 8) * 132 + j]     = acc[mt][n8][2] * s;
                fsm[(v + 8) * 132 + j + 1] = acc[mt][n8][3] * s;
            }
        __syncthreads();
        const int j  = tid >> 1;
        const int vb = (tid & 1) * 64;
        __half* dst = &updB[(long)(tile0 + j) * 384 + 256 + vb];
        #pragma unroll
        for (int i = 0; i < 16; i++) {
            const int v = vb + i * 4;
            *(uint2*)(dst + i * 4) = make_uint2(
                pack2(fsm[v * 132 + j],       fsm[(v + 1) * 132 + j]),
                pack2(fsm[(v + 2) * 132 + j], fsm[(v + 3) * 132 + j]));
        }
    }
}

__global__ __launch_bounds__(256, 2)
void agg_both(const float* __restrict__ adj,
              const __half* __restrict__ in_rep,
              const __half* __restrict__ out_rep,
              __half* __restrict__ upd16)
{
    extern __shared__ char smem[];
    if (blockIdx.z == 0) agg_body<false>(adj, in_rep,  upd16, smem);
    else                 agg_body<true >(adj, out_rep, upd16, smem);
}

// ===========================================================================
// final16: grid 256, CTA 64x128, K=384, 4-stage cp.async fp16 both operands.
// ===========================================================================
__global__ __launch_bounds__(256, 2)
void final16(const __half* __restrict__ upd16, const __half* __restrict__ Wupdh,
             const float* __restrict__ bias, float* __restrict__ out)
{
    extern __shared__ char sm[];
    const int tid  = threadIdx.x;
    const int lane = tid & 31;
    const int warp = tid >> 5;
    const int wm = warp >> 2, wn = warp & 3;
    const int g = lane >> 2, t = lane & 3;
    const int m0 = blockIdx.x * 64;

    const uint32_t smBase = (uint32_t)__cvta_generic_to_shared(sm);

    float acc[2][4][4];
    #pragma unroll
    for (int i = 0; i < 2; i++)
        #pragma unroll
        for (int j = 0; j < 4; j++)
            #pragma unroll
            for (int l = 0; l < 4; l++) acc[i][j][l] = 0.f;

    auto cpStage = [&](int st, int k0) {
        const uint32_t sA = smBase + st * 15360;
        const uint32_t sB = sA + 5120;
        {
            const int row = tid >> 2, ch = tid & 3;
            cp16(sA + row * 80 + ch * 16, upd16 + (long)(m0 + row) * 384 + k0 + ch * 8);
        }
        #pragma unroll
        for (int i = 0; i < 2; i++) {
            const int c = i * 256 + tid, row = c >> 2, ch = c & 3;
            cp16(sB + row * 80 + ch * 16, Wupdh + (long)row * 384 + k0 + ch * 8);
        }
    };

    auto compute = [&](int st) {
        const uint32_t sA = smBase + st * 15360;
        const uint32_t sB = sA + 5120;
        #pragma unroll
        for (int ks = 0; ks < 2; ks++) {
            const uint32_t kOff = ((lane >> 4) + 2 * ks) * 16;
            uint32_t aF[2][4], bR[2][4];
            #pragma unroll
            for (int mt = 0; mt < 2; mt++)
                ldsm4(aF[mt], sA + (wm * 32 + mt * 16 + (lane & 15)) * 80 + kOff);
            #pragma unroll
            for (int i = 0; i < 2; i++)
                ldsm4(bR[i], sB + (wn * 32 + i * 16 + (lane & 15)) * 80 + kOff);
            #pragma unroll
            for (int mt = 0; mt < 2; mt++)
                #pragma unroll
                for (int nt = 0; nt < 4; nt++)
                    mma16816(acc[mt][nt], aF[mt],
                             bR[nt >> 1][nt & 1], bR[nt >> 1][(nt & 1) + 2]);
        }
    };

    #pragma unroll
    for (int s = 0; s < 3; s++) { cpStage(s, s * 32); cp_commit(); }

    #pragma unroll 1
    for (int kt = 0; kt < 12; kt++) {
        cp_wait2();
        __syncthreads();
        const int nx = kt + 3;
        if (nx < 12) cpStage(nx & 3, nx * 32);
        cp_commit();
        compute(kt & 3);
    }

    #pragma unroll
    for (int mt = 0; mt < 2; mt++)
        #pragma unroll
        for (int nt = 0; nt < 4; nt++) {
            const int row = m0 + wm * 32 + mt * 16 + g;
            const int col = wn * 32 + nt * 8 + 2 * t;
            const float b0 = __ldg(bias + col), b1 = __ldg(bias + col + 1);
            float x0 = tanhf(acc[mt][nt][0] + b0), x1 = tanhf(acc[mt][nt][1] + b1);
            float x2 = tanhf(acc[mt][nt][2] + b0), x3 = tanhf(acc[mt][nt][3] + b1);
            *(float2*)&out[(long)row       * 128 + col] = make_float2(x0, x1);
            *(float2*)&out[(long)(row + 8) * 128 + col] = make_float2(x2, x3);
        }
}

// ===========================================================================
extern "C" void kernel_launch(void* const* d_in, const int* in_sizes, int n_in,
                              void* d_out, int out_size)
{
    const float* nodes  = (const float*)d_in[0];
    const float* adj    = (const float*)d_in[1];
    const float* W_in   = (const float*)d_in[2];
    const float* b_in   = (const float*)d_in[3];
    const float* W_out  = (const float*)d_in[4];
    const float* b_out  = (const float*)d_in[5];
    const float* W_node = (const float*)d_in[6];
    const float* b_node = (const float*)d_in[7];
    const float* W_upd  = (const float*)d_in[8];
    const float* b_upd  = (const float*)d_in[9];
    float* out = (float*)d_out;

    __half *in_rep, *out_rep, *upd16, *nodesh, *Wh, *Wupdh;
    cudaGetSymbolAddress((void**)&in_rep,  g_in_rep);
    cudaGetSymbolAddress((void**)&out_rep, g_out_rep);
    cudaGetSymbolAddress((void**)&upd16,   g_upd16);
    cudaGetSymbolAddress((void**)&nodesh,  g_nodesh);
    cudaGetSymbolAddress((void**)&Wh,      g_Wh);
    cudaGetSymbolAddress((void**)&Wupdh,   g_Wupdh);

    const int SMEM_PROJ  = 52224;
    const int SMEM_AGG   = 128 * 132 * 4;  // 67584
    const int SMEM_FINAL = 61440;
    cudaFuncSetAttribute(proj3h,
                         cudaFuncAttributeMaxDynamicSharedMemorySize, SMEM_PROJ);
    cudaFuncSetAttribute(agg_both,
                         cudaFuncAttributeMaxDynamicSharedMemorySize, SMEM_AGG);
    cudaFuncSetAttribute(final16,
                         cudaFuncAttributeMaxDynamicSharedMemorySize, SMEM_FINAL);

    // 0) one-shot fp16 conversion of nodes + all weights
    conv_h<<<1072, 256>>>(nodes, W_in, W_node, W_out, W_upd, nodesh, Wh, Wupdh);

    // 1) three ELU projections (all-fp16 operands)
    proj3h<<<dim3(256, 1, 3), 256, SMEM_PROJ>>>(nodesh, Wh, b_in, b_node, b_out,
                                                in_rep, out_rep, upd16);

    // 2+3) both aggregations (fp32 adj direct, streaming loads)
    agg_both<<<dim3(32, 4, 2), 256, SMEM_AGG>>>(adj, in_rep, out_rep, upd16);

    // 4) out = tanh(upd @ W_upd^T + b_upd)  (all-fp16 operands)
    final16<<<256, 256, SMEM_FINAL>>>(upd16, Wupdh, b_upd, out);
}

// round 15
// speedup vs baseline: 1.3875x; 1.0083x over previous
#include <cuda_runtime.h>
#include <cuda_fp16.h>
#include <cstdint>
#include <cmath>

// ---------------------------------------------------------------------------
// GraphSageLayer: B=4, N=4096, D_IN=128, REP=128, D_OUT=128
//
//  conv_h  : nodes, W_in/W_node/W_out, W_upd -> fp16 (one tiny streaming pass)
//  proj3h  : fp16 x fp16 ELU projections (cp.async, K=128 resident)
//  agg_both: (1 launch, z=2) fp32 adj direct (__ldcs); F staged ONE ITERATION
//            AHEAD (compute first, then stsF/ldF below it). 2 F bufs, 4 R stages.
//  final16 : fp16 x fp16 tanh GEMM over upd16, K=384, 4-stage cp.async, 3 CTA/SM
// ---------------------------------------------------------------------------

__device__ __half g_in_rep [4l * 4096 * 128];
__device__ __half g_out_rep[4l * 4096 * 128];
__device__ __half g_upd16  [4l * 4096 * 384];   // 12 MB
__device__ __half g_nodesh [16384l * 128];      // 4 MB
__device__ __half g_Wh     [3l * 128 * 128];    // z-order: in, node, out
__device__ __half g_Wupdh  [128l * 384];

__device__ __forceinline__ uint32_t pack2(float a, float b) {
    uint32_t r;
    asm("cvt.rn.f16x2.f32 %0, %1, %2;" : "=r"(r) : "f"(b), "f"(a));
    return r;
}
__device__ __forceinline__ void cp16(uint32_t dst, const void* src) {
    asm volatile("cp.async.cg.shared.global [%0], [%1], 16;" :: "r"(dst), "l"(src));
}
__device__ __forceinline__ void cp_commit() {
    asm volatile("cp.async.commit_group;");
}
__device__ __forceinline__ void cp_wait2() {
    asm volatile("cp.async.wait_group 2;");
}
__device__ __forceinline__ void cp_wait0() {
    asm volatile("cp.async.wait_group 0;");
}
__device__ __forceinline__ void ldsm4(uint32_t* r, uint32_t a) {
    asm volatile("ldmatrix.sync.aligned.m8n8.x4.shared.b16 {%0,%1,%2,%3}, [%4];"
        : "=r"(r[0]), "=r"(r[1]), "=r"(r[2]), "=r"(r[3]) : "r"(a));
}
__device__ __forceinline__ void ldsm4t(uint32_t* r, uint32_t a) {
    asm volatile("ldmatrix.sync.aligned.m8n8.x4.trans.shared.b16 {%0,%1,%2,%3}, [%4];"
        : "=r"(r[0]), "=r"(r[1]), "=r"(r[2]), "=r"(r[3]) : "r"(a));
}
__device__ __forceinline__ void mma16816(float* c, const uint32_t* a,
                                         uint32_t b0, uint32_t b1) {
    asm volatile(
        "mma.sync.aligned.m16n8k16.row.col.f32.f16.f16.f32 "
        "{%0,%1,%2,%3}, {%4,%5,%6,%7}, {%8,%9}, {%0,%1,%2,%3};\n"
        : "+f"(c[0]), "+f"(c[1]), "+f"(c[2]), "+f"(c[3])
        : "r"(a[0]), "r"(a[1]), "r"(a[2]), "r"(a[3]), "r"(b0), "r"(b1));
}

// ===========================================================================
// conv_h: fp32 -> fp16 for nodes + all weight matrices. 8 elems/thread.
// ===========================================================================
__global__ __launch_bounds__(256)
void conv_h(const float* __restrict__ nodes,
            const float* __restrict__ W_in, const float* __restrict__ W_node,
            const float* __restrict__ W_out, const float* __restrict__ W_upd,
            __half* __restrict__ nodesh, __half* __restrict__ Wh,
            __half* __restrict__ Wupdh)
{
    const int bx = blockIdx.x;
    const float* src; __half* dst; long g;
    if (bx < 1024)      { src = nodes;  dst = nodesh;     g = (long)bx * 256 + threadIdx.x; }
    else if (bx < 1032) { src = W_in;   dst = Wh;         g = (long)(bx - 1024) * 256 + threadIdx.x; }
    else if (bx < 1040) { src = W_node; dst = Wh + 16384; g = (long)(bx - 1032) * 256 + threadIdx.x; }
    else if (bx < 1048) { src = W_out;  dst = Wh + 32768; g = (long)(bx - 1040) * 256 + threadIdx.x; }
    else                { src = W_upd;  dst = Wupdh;      g = (long)(bx - 1048) * 256 + threadIdx.x; }
    float4 a = __ldcs((const float4*)src + 2 * g);
    float4 b = __ldcs((const float4*)src + 2 * g + 1);
    ((uint4*)dst)[g] = make_uint4(pack2(a.x, a.y), pack2(a.z, a.w),
                                  pack2(b.x, b.y), pack2(b.z, b.w));
}

// ===========================================================================
// proj3h: grid (256,1,3), 256 thr. CTA 64x128, K=128 fully resident fp16.
// ===========================================================================
__global__ __launch_bounds__(256, 2)
void proj3h(const __half* __restrict__ nodesh, const __half* __restrict__ Wh,
            const float* __restrict__ b_in, const float* __restrict__ b_node,
            const float* __restrict__ b_out,
            __half* __restrict__ in_rep, __half* __restrict__ out_rep,
            __half* __restrict__ upd16)
{
    extern __shared__ char sm[];
    const int tid  = threadIdx.x;
    const int lane = tid & 31;
    const int warp = tid >> 5;
    const int wm = warp >> 2, wn = warp & 3;
    const int g = lane >> 2, t = lane & 3;
    const int m0 = blockIdx.x * 64;
    const int z  = blockIdx.z;

    const __half* Wz  = Wh + z * 16384;
    const float* bias = (z == 0) ? b_in : (z == 1) ? b_node : b_out;

    const uint32_t sA = (uint32_t)__cvta_generic_to_shared(sm);
    const uint32_t sB = sA + 17408;

    #pragma unroll
    for (int i = 0; i < 4; i++) {
        const int c = i * 256 + tid, row = c >> 4, ch = c & 15;
        cp16(sA + row * 272 + ch * 16, nodesh + (long)(m0 + row) * 128 + ch * 8);
    }
    #pragma unroll
    for (int i = 0; i < 8; i++) {
        const int c = i * 256 + tid, row = c >> 4, ch = c & 15;
        cp16(sB + row * 272 + ch * 16, Wz + (long)row * 128 + ch * 8);
    }
    cp_commit();
    cp_wait0();
    __syncthreads();

    float acc[2][4][4];
    #pragma unroll
    for (int i = 0; i < 2; i++)
        #pragma unroll
        for (int j = 0; j < 4; j++)
            #pragma unroll
            for (int l = 0; l < 4; l++) acc[i][j][l] = 0.f;

    #pragma unroll
    for (int k = 0; k < 8; k++) {
        const uint32_t kOff = ((lane >> 4) + 2 * k) * 16;
        uint32_t aF[2][4], bR[2][4];
        #pragma unroll
        for (int mt = 0; mt < 2; mt++)
            ldsm4(aF[mt], sA + (wm * 32 + mt * 16 + (lane & 15)) * 272 + kOff);
        #pragma unroll
        for (int i = 0; i < 2; i++)
            ldsm4(bR[i], sB + (wn * 32 + i * 16 + (lane & 15)) * 272 + kOff);
        #pragma unroll
        for (int mt = 0; mt < 2; mt++)
            #pragma unroll
            for (int nt = 0; nt < 4; nt++)
                mma16816(acc[mt][nt], aF[mt],
                         bR[nt >> 1][nt & 1], bR[nt >> 1][(nt & 1) + 2]);
    }

    #pragma unroll
    for (int mt = 0; mt < 2; mt++)
        #pragma unroll
        for (int nt = 0; nt < 4; nt++) {
            const int row = m0 + wm * 32 + mt * 16 + g;
            const int col = wn * 32 + nt * 8 + 2 * t;
            const float b0 = __ldg(bias + col), b1 = __ldg(bias + col + 1);
            float x0 = acc[mt][nt][0] + b0, x1 = acc[mt][nt][1] + b1;
            float x2 = acc[mt][nt][2] + b0, x3 = acc[mt][nt][3] + b1;
            x0 = x0 > 0.f ? x0 : expm1f(x0);
            x1 = x1 > 0.f ? x1 : expm1f(x1);
            x2 = x2 > 0.f ? x2 : expm1f(x2);
            x3 = x3 > 0.f ? x3 : expm1f(x3);
            if (z == 1) {
                *(uint32_t*)&upd16[(long)row       * 384 + 128 + col] = pack2(x0, x1);
                *(uint32_t*)&upd16[(long)(row + 8) * 384 + 128 + col] = pack2(x2, x3);
            } else {
                __half* D = (z == 0) ? in_rep : out_rep;
                *(uint32_t*)&D[(long)row       * 128 + col] = pack2(x0, x1);
                *(uint32_t*)&D[(long)(row + 8) * 128 + col] = pack2(x2, x3);
            }
        }
}

// ===========================================================================
// Aggregation: CTA 128x128, BK=32. F (fp32 adj, __ldcs) staged ONE ITERATION
// AHEAD: iter kt = { wait; barrier; compute(kt); stsF(kt+1); ldF(kt+2); cpR }.
// F buf (kt+1)&1 written iter kt, read iter kt+1 (fenced by that barrier).
// fv holds exactly one tile (loaded iter kt-1, stored iter kt).
// ===========================================================================
template<bool OUTT>
__device__ __forceinline__ void agg_body(
    const float* __restrict__ adj, const __half* __restrict__ rep,
    __half* __restrict__ upd, char* smem)
{
    const int tid  = threadIdx.x;
    const int lane = tid & 31;
    const int warp = tid >> 5;
    const int wm   = warp >> 2;
    const int wn   = warp & 3;
    const int g    = lane >> 2;
    const int t    = lane & 3;
    const int tile0 = blockIdx.x * 128;
    const long b   = blockIdx.y;

    const float*  adjB = adj + b * (4096l * 4096);
    const __half* repB = rep + b * (4096l * 128);
    __half*       updB = upd + b * (4096l * 384);

    const uint32_t smBase = (uint32_t)__cvta_generic_to_shared(smem);
    const uint32_t sF0 = OUTT ? (smBase + 34816) : smBase;
    const int      FSTRIDE = OUTT ? 8704 : 10240;
    const uint32_t sR0 = OUTT ? smBase : (smBase + 20480);

    float acc[4][4][4];
    #pragma unroll
    for (int i = 0; i < 4; i++)
        #pragma unroll
        for (int j = 0; j < 4; j++)
            #pragma unroll
            for (int l = 0; l < 4; l++) acc[i][j][l] = 0.f;

    const int f_row = OUTT ? (tid >> 3) : (tid >> 1);
    const int f_ch  = OUTT ? (tid & 7)  : (tid & 1);
    const float* fSrcBase = OUTT
        ? (adjB + (long)f_row * 4096 + tile0 + f_ch * 16)
        : (adjB + (long)(tile0 + f_row) * 4096 + f_ch * 16);
    const uint32_t fDst = (OUTT ? f_row * 272 : f_row * 80) + f_ch * 32;

    float4 fv[4];
    auto ldF = [&](int k0) {
        const float* p = OUTT ? (fSrcBase + (long)k0 * 4096) : (fSrcBase + k0);
        #pragma unroll
        for (int i = 0; i < 4; i++) fv[i] = __ldcs((const float4*)p + i);
    };
    auto stsF = [&](int buf) {
        uint32_t w[8];
        #pragma unroll
        for (int i = 0; i < 4; i++) {
            w[2 * i]     = pack2(fv[i].x * 4096.f, fv[i].y * 4096.f);
            w[2 * i + 1] = pack2(fv[i].z * 4096.f, fv[i].w * 4096.f);
        }
        const uint32_t d = (sF0 - smBase) + buf * FSTRIDE + fDst;
        *(uint4*)(smem + d)      = make_uint4(w[0], w[1], w[2], w[3]);
        *(uint4*)(smem + d + 16) = make_uint4(w[4], w[5], w[6], w[7]);
    };

    const int r_k  = tid >> 4;
    const int r_nc = tid & 15;
    auto cpR = [&](int st, int k0) {
        const uint32_t sR = sR0 + st * 8704;
        cp16(sR + r_k * 272 + r_nc * 16,        repB + (long)(k0 + r_k) * 128 + r_nc * 8);
        cp16(sR + (r_k + 16) * 272 + r_nc * 16, repB + (long)(k0 + r_k + 16) * 128 + r_nc * 8);
    };

    auto compute = [&](int kt) {
        const uint32_t sA = OUTT ? (sR0 + (kt & 3) * 8704) : (sF0 + (kt & 1) * FSTRIDE);
        const uint32_t sB = OUTT ? (sF0 + (kt & 1) * FSTRIDE) : (sR0 + (kt & 3) * 8704);
        #pragma unroll
        for (int ks = 0; ks < 2; ks++) {
            uint32_t aF[4][4], bF[2][4];
            #pragma unroll
            for (int mt = 0; mt < 4; mt++) {
                if (!OUTT) {
                    ldsm4(aF[mt], sA + (wm * 64 + mt * 16 + (lane & 15)) * 80
                                     + ((lane >> 4) + 2 * ks) * 16);
                } else {
                    ldsm4t(aF[mt], sA + ((lane & 7) + (lane >> 4) * 8 + 16 * ks) * 272
                                      + (wm * 64 + mt * 16 + ((lane >> 3) & 1) * 8) * 2);
                }
            }
            #pragma unroll
            for (int nt = 0; nt < 2; nt++)
                ldsm4t(bF[nt], sB + ((lane & 15) + 16 * ks) * 272
                                  + wn * 64 + nt * 32 + (lane >> 4) * 16);
            #pragma unroll
            for (int mt = 0; mt < 4; mt++)
                #pragma unroll
                for (int n8 = 0; n8 < 4; n8++)
                    mma16816(acc[mt][n8], aF[mt],
                             bF[n8 >> 1][(n8 & 1) * 2], bF[n8 >> 1][(n8 & 1) * 2 + 1]);
        }
    };

    // prologue: F tile 0 -> buf 0; F tile 1 in regs; R stages 0..2 in flight
    ldF(0);
    stsF(0);
    ldF(32);
    #pragma unroll
    for (int s = 0; s < 3; s++) { cpR(s, s * 32); cp_commit(); }

    #pragma unroll 1
    for (int kt = 0; kt < 128; kt++) {
        cp_wait2();
        __syncthreads();
        compute(kt);                                // F buf kt&1 staged LAST iter
        if (kt + 1 < 128) stsF((kt + 1) & 1);       // store tile kt+1 (regs from iter kt-1)
        if (kt + 2 < 128) ldF((kt + 2) * 32);       // full-iteration LDG window
        const int nx = kt + 3;
        if (nx < 128) cpR(nx & 3, nx * 32);
        cp_commit();
    }

    const float s = 1.f / 4096.f;
    if (!OUTT) {
        #pragma unroll
        for (int mt = 0; mt < 4; mt++)
            #pragma unroll
            for (int n8 = 0; n8 < 4; n8++) {
                const int row = tile0 + wm * 64 + mt * 16 + g;
                const int col = wn * 32 + n8 * 8 + 2 * t;
                *(uint32_t*)&updB[(long)row * 384 + col] =
                    pack2(acc[mt][n8][0] * s, acc[mt][n8][1] * s);
                *(uint32_t*)&updB[(long)(row + 8) * 384 + col] =
                    pack2(acc[mt][n8][2] * s, acc[mt][n8][3] * s);
            }
    } else {
        __syncthreads();
        float* fsm = (float*)smem;   // [v][132] = 67584 B
        #pragma unroll
        for (int mt = 0; mt < 4; mt++)
            #pragma unroll
            for (int n8 = 0; n8 < 4; n8++) {
                const int v = wm * 64 + mt * 16 + g;
                const int j = wn * 32 + n8 * 8 + 2 * t;
                fsm[v * 132 + j]           = acc[mt][n8][0] * s;
                fsm[v * 132 + j + 1]       = acc[mt][n8][1] * s;
                fsm[(v + 8) * 132 + j]     = acc[mt][n8][2] * s;
                fsm[(v + 8) * 132 + j + 1] = acc[mt][n8][3] * s;
            }
        __syncthreads();
        const int j  = tid >> 1;
        const int vb = (tid & 1) * 64;
        __half* dst = &updB[(long)(tile0 + j) * 384 + 256 + vb];
        #pragma unroll
        for (int i = 0; i < 16; i++) {
            const int v = vb + i * 4;
            *(uint2*)(dst + i * 4) = make_uint2(
                pack2(fsm[v * 132 + j],       fsm[(v + 1) * 132 + j]),
                pack2(fsm[(v + 2) * 132 + j], fsm[(v + 3) * 132 + j]));
        }
    }
}

__global__ __launch_bounds__(256, 2)
void agg_both(const float* __restrict__ adj,
              const __half* __restrict__ in_rep,
              const __half* __restrict__ out_rep,
              __half* __restrict__ upd16)
{
    extern __shared__ char smem[];
    if (blockIdx.z == 0) agg_body<false>(adj, in_rep,  upd16, smem);
    else                 agg_body<true >(adj, out_rep, upd16, smem);
}

// ===========================================================================
// final16: grid 256, CTA 64x128, K=384, 4-stage cp.async fp16, 3 CTA/SM.
// ===========================================================================
__global__ __launch_bounds__(256, 3)
void final16(const __half* __restrict__ upd16, const __half* __restrict__ Wupdh,
             const float* __restrict__ bias, float* __restrict__ out)
{
    extern __shared__ char sm[];
    const int tid  = threadIdx.x;
    const int lane = tid & 31;
    const int warp = tid >> 5;
    const int wm = warp >> 2, wn = warp & 3;
    const int g = lane >> 2, t = lane & 3;
    const int m0 = blockIdx.x * 64;

    const uint32_t smBase = (uint32_t)__cvta_generic_to_shared(sm);

    float acc[2][4][4];
    #pragma unroll
    for (int i = 0; i < 2; i++)
        #pragma unroll
        for (int j = 0; j < 4; j++)
            #pragma unroll
            for (int l = 0; l < 4; l++) acc[i][j][l] = 0.f;

    auto cpStage = [&](int st, int k0) {
        const uint32_t sA = smBase + st * 15360;
        const uint32_t sB = sA + 5120;
        {
            const int row = tid >> 2, ch = tid & 3;
            cp16(sA + row * 80 + ch * 16, upd16 + (long)(m0 + row) * 384 + k0 + ch * 8);
        }
        #pragma unroll
        for (int i = 0; i < 2; i++) {
            const int c = i * 256 + tid, row = c >> 2, ch = c & 3;
            cp16(sB + row * 80 + ch * 16, Wupdh + (long)row * 384 + k0 + ch * 8);
        }
    };

    auto compute = [&](int st) {
        const uint32_t sA = smBase + st * 15360;
        const uint32_t sB = sA + 5120;
        #pragma unroll
        for (int ks = 0; ks < 2; ks++) {
            const uint32_t kOff = ((lane >> 4) + 2 * ks) * 16;
            uint32_t aF[2][4], bR[2][4];
            #pragma unroll
            for (int mt = 0; mt < 2; mt++)
                ldsm4(aF[mt], sA + (wm * 32 + mt * 16 + (lane & 15)) * 80 + kOff);
            #pragma unroll
            for (int i = 0; i < 2; i++)
                ldsm4(bR[i], sB + (wn * 32 + i * 16 + (lane & 15)) * 80 + kOff);
            #pragma unroll
            for (int mt = 0; mt < 2; mt++)
                #pragma unroll
                for (int nt = 0; nt < 4; nt++)
                    mma16816(acc[mt][nt], aF[mt],
                             bR[nt >> 1][nt & 1], bR[nt >> 1][(nt & 1) + 2]);
        }
    };

    #pragma unroll
    for (int s = 0; s < 3; s++) { cpStage(s, s * 32); cp_commit(); }

    #pragma unroll 1
    for (int kt = 0; kt < 12; kt++) {
        cp_wait2();
        __syncthreads();
        const int nx = kt + 3;
        if (nx < 12) cpStage(nx & 3, nx * 32);
        cp_commit();
        compute(kt & 3);
    }

    #pragma unroll
    for (int mt = 0; mt < 2; mt++)
        #pragma unroll
        for (int nt = 0; nt < 4; nt++) {
            const int row = m0 + wm * 32 + mt * 16 + g;
            const int col = wn * 32 + nt * 8 + 2 * t;
            const float b0 = __ldg(bias + col), b1 = __ldg(bias + col + 1);
            float x0 = tanhf(acc[mt][nt][0] + b0), x1 = tanhf(acc[mt][nt][1] + b1);
            float x2 = tanhf(acc[mt][nt][2] + b0), x3 = tanhf(acc[mt][nt][3] + b1);
            *(float2*)&out[(long)row       * 128 + col] = make_float2(x0, x1);
            *(float2*)&out[(long)(row + 8) * 128 + col] = make_float2(x2, x3);
        }
}

// ===========================================================================
extern "C" void kernel_launch(void* const* d_in, const int* in_sizes, int n_in,
                              void* d_out, int out_size)
{
    const float* nodes  = (const float*)d_in[0];
    const float* adj    = (const float*)d_in[1];
    const float* W_in   = (const float*)d_in[2];
    const float* b_in   = (const float*)d_in[3];
    const float* W_out  = (const float*)d_in[4];
    const float* b_out  = (const float*)d_in[5];
    const float* W_node = (const float*)d_in[6];
    const float* b_node = (const float*)d_in[7];
    const float* W_upd  = (const float*)d_in[8];
    const float* b_upd  = (const float*)d_in[9];
    float* out = (float*)d_out;

    __half *in_rep, *out_rep, *upd16, *nodesh, *Wh, *Wupdh;
    cudaGetSymbolAddress((void**)&in_rep,  g_in_rep);
    cudaGetSymbolAddress((void**)&out_rep, g_out_rep);
    cudaGetSymbolAddress((void**)&upd16,   g_upd16);
    cudaGetSymbolAddress((void**)&nodesh,  g_nodesh);
    cudaGetSymbolAddress((void**)&Wh,      g_Wh);
    cudaGetSymbolAddress((void**)&Wupdh,   g_Wupdh);

    const int SMEM_PROJ  = 52224;
    const int SMEM_AGG   = 128 * 132 * 4;  // 67584
    const int SMEM_FINAL = 61440;
    cudaFuncSetAttribute(proj3h,
                         cudaFuncAttributeMaxDynamicSharedMemorySize, SMEM_PROJ);
    cudaFuncSetAttribute(agg_both,
                         cudaFuncAttributeMaxDynamicSharedMemorySize, SMEM_AGG);
    cudaFuncSetAttribute(final16,
                         cudaFuncAttributeMaxDynamicSharedMemorySize, SMEM_FINAL);

    // 0) one-shot fp16 conversion of nodes + all weights
    conv_h<<<1072, 256>>>(nodes, W_in, W_node, W_out, W_upd, nodesh, Wh, Wupdh);

    // 1) three ELU projections (all-fp16 operands)
    proj3h<<<dim3(256, 1, 3), 256, SMEM_PROJ>>>(nodesh, Wh, b_in, b_node, b_out,
                                                in_rep, out_rep, upd16);

    // 2+3) both aggregations (fp32 adj direct; F staged one iter ahead)
    agg_both<<<dim3(32, 4, 2), 256, SMEM_AGG>>>(adj, in_rep, out_rep, upd16);

    // 4) out = tanh(upd @ W_upd^T + b_upd)  (all-fp16 operands)
    final16<<<256, 256, SMEM_FINAL>>>(upd16, Wupdh, b_upd, out);
}

// round 16
// speedup vs baseline: 1.3903x; 1.0020x over previous
#include <cuda_runtime.h>
#include <cuda_fp16.h>
#include <cstdint>
#include <cmath>

// ---------------------------------------------------------------------------
// GraphSageLayer: B=4, N=4096, D_IN=128, REP=128, D_OUT=128
//
//  conv_h  : nodes + all W -> fp16 (tiny streaming pass)
//  proj3h  : fp16 x fp16 ELU projections (cp.async, K=128 resident)
//  agg_both: (1 launch, z=2) fp32 adj direct (__ldcs). TWO ktiles per barrier:
//            4 F bufs (fp16, staged from regs), 4 R cp.async stages.
//  final16 : fp16 x fp16 tanh GEMM over upd16, K=384, 4-stage cp.async
// ---------------------------------------------------------------------------

__device__ __half g_in_rep [4l * 4096 * 128];
__device__ __half g_out_rep[4l * 4096 * 128];
__device__ __half g_upd16  [4l * 4096 * 384];
__device__ __half g_nodesh [16384l * 128];
__device__ __half g_Wh     [3l * 128 * 128];
__device__ __half g_Wupdh  [128l * 384];

__device__ __forceinline__ uint32_t pack2(float a, float b) {
    uint32_t r;
    asm("cvt.rn.f16x2.f32 %0, %1, %2;" : "=r"(r) : "f"(b), "f"(a));
    return r;
}
__device__ __forceinline__ void cp16(uint32_t dst, const void* src) {
    asm volatile("cp.async.cg.shared.global [%0], [%1], 16;" :: "r"(dst), "l"(src));
}
__device__ __forceinline__ void cp_commit() {
    asm volatile("cp.async.commit_group;");
}
__device__ __forceinline__ void cp_wait2() {
    asm volatile("cp.async.wait_group 2;");
}
__device__ __forceinline__ void cp_wait0() {
    asm volatile("cp.async.wait_group 0;");
}
__device__ __forceinline__ void ldsm4(uint32_t* r, uint32_t a) {
    asm volatile("ldmatrix.sync.aligned.m8n8.x4.shared.b16 {%0,%1,%2,%3}, [%4];"
        : "=r"(r[0]), "=r"(r[1]), "=r"(r[2]), "=r"(r[3]) : "r"(a));
}
__device__ __forceinline__ void ldsm4t(uint32_t* r, uint32_t a) {
    asm volatile("ldmatrix.sync.aligned.m8n8.x4.trans.shared.b16 {%0,%1,%2,%3}, [%4];"
        : "=r"(r[0]), "=r"(r[1]), "=r"(r[2]), "=r"(r[3]) : "r"(a));
}
__device__ __forceinline__ void mma16816(float* c, const uint32_t* a,
                                         uint32_t b0, uint32_t b1) {
    asm volatile(
        "mma.sync.aligned.m16n8k16.row.col.f32.f16.f16.f32 "
        "{%0,%1,%2,%3}, {%4,%5,%6,%7}, {%8,%9}, {%0,%1,%2,%3};\n"
        : "+f"(c[0]), "+f"(c[1]), "+f"(c[2]), "+f"(c[3])
        : "r"(a[0]), "r"(a[1]), "r"(a[2]), "r"(a[3]), "r"(b0), "r"(b1));
}

// ===========================================================================
__global__ __launch_bounds__(256)
void conv_h(const float* __restrict__ nodes,
            const float* __restrict__ W_in, const float* __restrict__ W_node,
            const float* __restrict__ W_out, const float* __restrict__ W_upd,
            __half* __restrict__ nodesh, __half* __restrict__ Wh,
            __half* __restrict__ Wupdh)
{
    const int bx = blockIdx.x;
    const float* src; __half* dst; long g;
    if (bx < 1024)      { src = nodes;  dst = nodesh;     g = (long)bx * 256 + threadIdx.x; }
    else if (bx < 1032) { src = W_in;   dst = Wh;         g = (long)(bx - 1024) * 256 + threadIdx.x; }
    else if (bx < 1040) { src = W_node; dst = Wh + 16384; g = (long)(bx - 1032) * 256 + threadIdx.x; }
    else if (bx < 1048) { src = W_out;  dst = Wh + 32768; g = (long)(bx - 1040) * 256 + threadIdx.x; }
    else                { src = W_upd;  dst = Wupdh;      g = (long)(bx - 1048) * 256 + threadIdx.x; }
    float4 a = __ldcs((const float4*)src + 2 * g);
    float4 b = __ldcs((const float4*)src + 2 * g + 1);
    ((uint4*)dst)[g] = make_uint4(pack2(a.x, a.y), pack2(a.z, a.w),
                                  pack2(b.x, b.y), pack2(b.z, b.w));
}

// ===========================================================================
__global__ __launch_bounds__(256, 2)
void proj3h(const __half* __restrict__ nodesh, const __half* __restrict__ Wh,
            const float* __restrict__ b_in, const float* __restrict__ b_node,
            const float* __restrict__ b_out,
            __half* __restrict__ in_rep, __half* __restrict__ out_rep,
            __half* __restrict__ upd16)
{
    extern __shared__ char sm[];
    const int tid  = threadIdx.x;
    const int lane = tid & 31;
    const int warp = tid >> 5;
    const int wm = warp >> 2, wn = warp & 3;
    const int g = lane >> 2, t = lane & 3;
    const int m0 = blockIdx.x * 64;
    const int z  = blockIdx.z;

    const __half* Wz  = Wh + z * 16384;
    const float* bias = (z == 0) ? b_in : (z == 1) ? b_node : b_out;

    const uint32_t sA = (uint32_t)__cvta_generic_to_shared(sm);
    const uint32_t sB = sA + 17408;

    #pragma unroll
    for (int i = 0; i < 4; i++) {
        const int c = i * 256 + tid, row = c >> 4, ch = c & 15;
        cp16(sA + row * 272 + ch * 16, nodesh + (long)(m0 + row) * 128 + ch * 8);
    }
    #pragma unroll
    for (int i = 0; i < 8; i++) {
        const int c = i * 256 + tid, row = c >> 4, ch = c & 15;
        cp16(sB + row * 272 + ch * 16, Wz + (long)row * 128 + ch * 8);
    }
    cp_commit();
    cp_wait0();
    __syncthreads();

    float acc[2][4][4];
    #pragma unroll
    for (int i = 0; i < 2; i++)
        #pragma unroll
        for (int j = 0; j < 4; j++)
            #pragma unroll
            for (int l = 0; l < 4; l++) acc[i][j][l] = 0.f;

    #pragma unroll
    for (int k = 0; k < 8; k++) {
        const uint32_t kOff = ((lane >> 4) + 2 * k) * 16;
        uint32_t aF[2][4], bR[2][4];
        #pragma unroll
        for (int mt = 0; mt < 2; mt++)
            ldsm4(aF[mt], sA + (wm * 32 + mt * 16 + (lane & 15)) * 272 + kOff);
        #pragma unroll
        for (int i = 0; i < 2; i++)
            ldsm4(bR[i], sB + (wn * 32 + i * 16 + (lane & 15)) * 272 + kOff);
        #pragma unroll
        for (int mt = 0; mt < 2; mt++)
            #pragma unroll
            for (int nt = 0; nt < 4; nt++)
                mma16816(acc[mt][nt], aF[mt],
                         bR[nt >> 1][nt & 1], bR[nt >> 1][(nt & 1) + 2]);
    }

    #pragma unroll
    for (int mt = 0; mt < 2; mt++)
        #pragma unroll
        for (int nt = 0; nt < 4; nt++) {
            const int row = m0 + wm * 32 + mt * 16 + g;
            const int col = wn * 32 + nt * 8 + 2 * t;
            const float b0 = __ldg(bias + col), b1 = __ldg(bias + col + 1);
            float x0 = acc[mt][nt][0] + b0, x1 = acc[mt][nt][1] + b1;
            float x2 = acc[mt][nt][2] + b0, x3 = acc[mt][nt][3] + b1;
            x0 = x0 > 0.f ? x0 : expm1f(x0);
            x1 = x1 > 0.f ? x1 : expm1f(x1);
            x2 = x2 > 0.f ? x2 : expm1f(x2);
            x3 = x3 > 0.f ? x3 : expm1f(x3);
            if (z == 1) {
                *(uint32_t*)&upd16[(long)row       * 384 + 128 + col] = pack2(x0, x1);
                *(uint32_t*)&upd16[(long)(row + 8) * 384 + 128 + col] = pack2(x2, x3);
            } else {
                __half* D = (z == 0) ? in_rep : out_rep;
                *(uint32_t*)&D[(long)row       * 128 + col] = pack2(x0, x1);
                *(uint32_t*)&D[(long)(row + 8) * 128 + col] = pack2(x2, x3);
            }
        }
}

// ===========================================================================
// Aggregation: CTA 128x128, BK=32 tiles, TWO tiles per barrier (64 iters).
// SMEM: R stages @0 (4 x 8704 = 34816), F bufs @34816 (4 x FSTRIDE).
//  iter j (t0=2j): wait0; barrier; cpR(t0+2,t0+3); compute(t0); compute(t0+1);
//                  stsF(t0+2,t0+3) [regs from iter j-1]; ldF(t0+4,t0+5).
// ===========================================================================
template<bool OUTT>
__device__ __forceinline__ void agg_body(
    const float* __restrict__ adj, const __half* __restrict__ rep,
    __half* __restrict__ upd, char* smem)
{
    const int tid  = threadIdx.x;
    const int lane = tid & 31;
    const int warp = tid >> 5;
    const int wm   = warp >> 2;
    const int wn   = warp & 3;
    const int g    = lane >> 2;
    const int t    = lane & 3;
    const int tile0 = blockIdx.x * 128;
    const long b   = blockIdx.y;

    const float*  adjB = adj + b * (4096l * 4096);
    const __half* repB = rep + b * (4096l * 128);
    __half*       updB = upd + b * (4096l * 384);

    const uint32_t smBase = (uint32_t)__cvta_generic_to_shared(smem);
    const uint32_t sR0 = smBase;                 // 4 x 8704
    const uint32_t sF0 = smBase + 34816;         // 4 x FSTRIDE
    const int      FSTRIDE = OUTT ? 8704 : 10240;

    float acc[4][4][4];
    #pragma unroll
    for (int i = 0; i < 4; i++)
        #pragma unroll
        for (int j = 0; j < 4; j++)
            #pragma unroll
            for (int l = 0; l < 4; l++) acc[i][j][l] = 0.f;

    const int f_row = OUTT ? (tid >> 3) : (tid >> 1);
    const int f_ch  = OUTT ? (tid & 7)  : (tid & 1);
    const float* fSrcBase = OUTT
        ? (adjB + (long)f_row * 4096 + tile0 + f_ch * 16)
        : (adjB + (long)(tile0 + f_row) * 4096 + f_ch * 16);
    const uint32_t fDst = (OUTT ? f_row * 272 : f_row * 80) + f_ch * 32;

    float4 fvA[4], fvB[4];
    // load tiles t0 and t0+1 into fvA / fvB
    auto ldF2 = [&](int t0k) {
        if (!OUTT) {
            const float* p = fSrcBase + t0k * 32;
            #pragma unroll
            for (int i = 0; i < 4; i++) fvA[i] = __ldcs((const float4*)p + i);
            p += 32;
            #pragma unroll
            for (int i = 0; i < 4; i++) fvB[i] = __ldcs((const float4*)p + i);
        } else {
            const float* p = fSrcBase + (long)t0k * 32 * 4096;
            #pragma unroll
            for (int i = 0; i < 4; i++) fvA[i] = __ldcs((const float4*)p + i);
            p += 32l * 4096;
            #pragma unroll
            for (int i = 0; i < 4; i++) fvB[i] = __ldcs((const float4*)p + i);
        }
    };
    auto stsOne = [&](int buf, const float4* fv) {
        uint32_t w[8];
        #pragma unroll
        for (int i = 0; i < 4; i++) {
            w[2 * i]     = pack2(fv[i].x * 4096.f, fv[i].y * 4096.f);
            w[2 * i + 1] = pack2(fv[i].z * 4096.f, fv[i].w * 4096.f);
        }
        const uint32_t d = (sF0 - smBase) + buf * FSTRIDE + fDst;
        *(uint4*)(smem + d)      = make_uint4(w[0], w[1], w[2], w[3]);
        *(uint4*)(smem + d + 16) = make_uint4(w[4], w[5], w[6], w[7]);
    };
    auto stsF2 = [&](int t0k) {
        stsOne(t0k & 3, fvA);
        stsOne((t0k + 1) & 3, fvB);
    };

    const int r_k  = tid >> 4;
    const int r_nc = tid & 15;
    auto cpR1 = [&](int tk) {
        const uint32_t sR = sR0 + (tk & 3) * 8704;
        const int k0 = tk * 32;
        cp16(sR + r_k * 272 + r_nc * 16,        repB + (long)(k0 + r_k) * 128 + r_nc * 8);
        cp16(sR + (r_k + 16) * 272 + r_nc * 16, repB + (long)(k0 + r_k + 16) * 128 + r_nc * 8);
    };

    auto compute = [&](int kt) {
        const uint32_t sFb = sF0 + (kt & 3) * FSTRIDE;
        const uint32_t sRb = sR0 + (kt & 3) * 8704;
        const uint32_t sA = OUTT ? sRb : sFb;
        const uint32_t sB = OUTT ? sFb : sRb;
        #pragma unroll
        for (int ks = 0; ks < 2; ks++) {
            uint32_t aF[4][4], bF[2][4];
            #pragma unroll
            for (int mt = 0; mt < 4; mt++) {
                if (!OUTT) {
                    ldsm4(aF[mt], sA + (wm * 64 + mt * 16 + (lane & 15)) * 80
                                     + ((lane >> 4) + 2 * ks) * 16);
                } else {
                    ldsm4t(aF[mt], sA + ((lane & 7) + (lane >> 4) * 8 + 16 * ks) * 272
                                      + (wm * 64 + mt * 16 + ((lane >> 3) & 1) * 8) * 2);
                }
            }
            #pragma unroll
            for (int nt = 0; nt < 2; nt++)
                ldsm4t(bF[nt], sB + ((lane & 15) + 16 * ks) * 272
                                  + wn * 64 + nt * 32 + (lane >> 4) * 16);
            #pragma unroll
            for (int mt = 0; mt < 4; mt++)
                #pragma unroll
                for (int n8 = 0; n8 < 4; n8++)
                    mma16816(acc[mt][n8], aF[mt],
                             bF[n8 >> 1][(n8 & 1) * 2], bF[n8 >> 1][(n8 & 1) * 2 + 1]);
        }
    };

    // prologue: F tiles 0,1 -> bufs 0,1; F tiles 2,3 in regs; R tiles 0,1 committed
    ldF2(0);
    stsF2(0);
    ldF2(2);
    cpR1(0); cpR1(1);
    cp_commit();

    #pragma unroll 1
    for (int j = 0; j < 64; j++) {
        const int t0 = 2 * j;
        cp_wait0();                 // R tiles t0,t0+1 landed
        __syncthreads();            // F bufs t0,t0+1 (stsF'd last iter) visible
        if (t0 + 2 < 128) { cpR1(t0 + 2); cpR1(t0 + 3); }
        cp_commit();
        compute(t0);
        compute(t0 + 1);
        if (t0 + 2 < 128) stsF2(t0 + 2);   // regs loaded last iteration
        if (t0 + 4 < 128) ldF2(t0 + 4);
    }

    const float s = 1.f / 4096.f;
    if (!OUTT) {
        #pragma unroll
        for (int mt = 0; mt < 4; mt++)
            #pragma unroll
            for (int n8 = 0; n8 < 4; n8++) {
                const int row = tile0 + wm * 64 + mt * 16 + g;
                const int col = wn * 32 + n8 * 8 + 2 * t;
                *(uint32_t*)&updB[(long)row * 384 + col] =
                    pack2(acc[mt][n8][0] * s, acc[mt][n8][1] * s);
                *(uint32_t*)&updB[(long)(row + 8) * 384 + col] =
                    pack2(acc[mt][n8][2] * s, acc[mt][n8][3] * s);
            }
    } else {
        __syncthreads();
        float* fsm = (float*)smem;   // [v][132] = 67584 B < 75776 alloc
        #pragma unroll
        for (int mt = 0; mt < 4; mt++)
            #pragma unroll
            for (int n8 = 0; n8 < 4; n8++) {
                const int v = wm * 64 + mt * 16 + g;
                const int j = wn * 32 + n8 * 8 + 2 * t;
                fsm[v * 132 + j]           = acc[mt][n8][0] * s;
                fsm[v * 132 + j + 1]       = acc[mt][n8][1] * s;
                fsm[(v + 8) * 132 + j]     = acc[mt][n8][2] * s;
                fsm[(v + 8) * 132 + j + 1] = acc[mt][n8][3] * s;
            }
        __syncthreads();
        const int j  = tid >> 1;
        const int vb = (tid & 1) * 64;
        __half* dst = &updB[(long)(tile0 + j) * 384 + 256 + vb];
        #pragma unroll
        for (int i = 0; i < 16; i++) {
            const int v = vb + i * 4;
            *(uint2*)(dst + i * 4) = make_uint2(
                pack2(fsm[v * 132 + j],       fsm[(v + 1) * 132 + j]),
                pack2(fsm[(v + 2) * 132 + j], fsm[(v + 3) * 132 + j]));
        }
    }
}

__global__ __launch_bounds__(256, 2)
void agg_both(const float* __restrict__ adj,
              const __half* __restrict__ in_rep,
              const __half* __restrict__ out_rep,
              __half* __restrict__ upd16)
{
    extern __shared__ char smem[];
    if (blockIdx.z == 0) agg_body<false>(adj, in_rep,  upd16, smem);
    else                 agg_body<true >(adj, out_rep, upd16, smem);
}

// ===========================================================================
__global__ __launch_bounds__(256, 3)
void final16(const __half* __restrict__ upd16, const __half* __restrict__ Wupdh,
             const float* __restrict__ bias, float* __restrict__ out)
{
    extern __shared__ char sm[];
    const int tid  = threadIdx.x;
    const int lane = tid & 31;
    const int warp = tid >> 5;
    const int wm = warp >> 2, wn = warp & 3;
    const int g = lane >> 2, t = lane & 3;
    const int m0 = blockIdx.x * 64;

    const uint32_t smBase = (uint32_t)__cvta_generic_to_shared(sm);

    float acc[2][4][4];
    #pragma unroll
    for (int i = 0; i < 2; i++)
        #pragma unroll
        for (int j = 0; j < 4; j++)
            #pragma unroll
            for (int l = 0; l < 4; l++) acc[i][j][l] = 0.f;

    auto cpStage = [&](int st, int k0) {
        const uint32_t sA = smBase + st * 15360;
        const uint32_t sB = sA + 5120;
        {
            const int row = tid >> 2, ch = tid & 3;
            cp16(sA + row * 80 + ch * 16, upd16 + (long)(m0 + row) * 384 + k0 + ch * 8);
        }
        #pragma unroll
        for (int i = 0; i < 2; i++) {
            const int c = i * 256 + tid, row = c >> 2, ch = c & 3;
            cp16(sB + row * 80 + ch * 16, Wupdh + (long)row * 384 + k0 + ch * 8);
        }
    };

    auto compute = [&](int st) {
        const uint32_t sA = smBase + st * 15360;
        const uint32_t sB = sA + 5120;
        #pragma unroll
        for (int ks = 0; ks < 2; ks++) {
            const uint32_t kOff = ((lane >> 4) + 2 * ks) * 16;
            uint32_t aF[2][4], bR[2][4];
            #pragma unroll
            for (int mt = 0; mt < 2; mt++)
                ldsm4(aF[mt], sA + (wm * 32 + mt * 16 + (lane & 15)) * 80 + kOff);
            #pragma unroll
            for (int i = 0; i < 2; i++)
                ldsm4(bR[i], sB + (wn * 32 + i * 16 + (lane & 15)) * 80 + kOff);
            #pragma unroll
            for (int mt = 0; mt < 2; mt++)
                #pragma unroll
                for (int nt = 0; nt < 4; nt++)
                    mma16816(acc[mt][nt], aF[mt],
                             bR[nt >> 1][nt & 1], bR[nt >> 1][(nt & 1) + 2]);
        }
    };

    #pragma unroll
    for (int s = 0; s < 3; s++) { cpStage(s, s * 32); cp_commit(); }

    #pragma unroll 1
    for (int kt = 0; kt < 12; kt++) {
        cp_wait2();
        __syncthreads();
        const int nx = kt + 3;
        if (nx < 12) cpStage(nx & 3, nx * 32);
        cp_commit();
        compute(kt & 3);
    }

    #pragma unroll
    for (int mt = 0; mt < 2; mt++)
        #pragma unroll
        for (int nt = 0; nt < 4; nt++) {
            const int row = m0 + wm * 32 + mt * 16 + g;
            const int col = wn * 32 + nt * 8 + 2 * t;
            const float b0 = __ldg(bias + col), b1 = __ldg(bias + col + 1);
            float x0 = tanhf(acc[mt][nt][0] + b0), x1 = tanhf(acc[mt][nt][1] + b1);
            float x2 = tanhf(acc[mt][nt][2] + b0), x3 = tanhf(acc[mt][nt][3] + b1);
            *(float2*)&out[(long)row       * 128 + col] = make_float2(x0, x1);
            *(float2*)&out[(long)(row + 8) * 128 + col] = make_float2(x2, x3);
        }
}

// ===========================================================================
extern "C" void kernel_launch(void* const* d_in, const int* in_sizes, int n_in,
                              void* d_out, int out_size)
{
    const float* nodes  = (const float*)d_in[0];
    const float* adj    = (const float*)d_in[1];
    const float* W_in   = (const float*)d_in[2];
    const float* b_in   = (const float*)d_in[3];
    const float* W_out  = (const float*)d_in[4];
    const float* b_out  = (const float*)d_in[5];
    const float* W_node = (const float*)d_in[6];
    const float* b_node = (const float*)d_in[7];
    const float* W_upd  = (const float*)d_in[8];
    const float* b_upd  = (const float*)d_in[9];
    float* out = (float*)d_out;

    __half *in_rep, *out_rep, *upd16, *nodesh, *Wh, *Wupdh;
    cudaGetSymbolAddress((void**)&in_rep,  g_in_rep);
    cudaGetSymbolAddress((void**)&out_rep, g_out_rep);
    cudaGetSymbolAddress((void**)&upd16,   g_upd16);
    cudaGetSymbolAddress((void**)&nodesh,  g_nodesh);
    cudaGetSymbolAddress((void**)&Wh,      g_Wh);
    cudaGetSymbolAddress((void**)&Wupdh,   g_Wupdh);

    const int SMEM_PROJ  = 52224;
    const int SMEM_AGG   = 34816 + 4 * 10240;  // 75776 (R 4 stages + F 4 bufs)
    const int SMEM_FINAL = 61440;
    cudaFuncSetAttribute(proj3h,
                         cudaFuncAttributeMaxDynamicSharedMemorySize, SMEM_PROJ);
    cudaFuncSetAttribute(agg_both,
                         cudaFuncAttributeMaxDynamicSharedMemorySize, SMEM_AGG);
    cudaFuncSetAttribute(final16,
                         cudaFuncAttributeMaxDynamicSharedMemorySize, SMEM_FINAL);

    // 0) one-shot fp16 conversion of nodes + all weights
    conv_h<<<1072, 256>>>(nodes, W_in, W_node, W_out, W_upd, nodesh, Wh, Wupdh);

    // 1) three ELU projections (all-fp16 operands)
    proj3h<<<dim3(256, 1, 3), 256, SMEM_PROJ>>>(nodesh, Wh, b_in, b_node, b_out,
                                                in_rep, out_rep, upd16);

    // 2+3) both aggregations (two ktiles per barrier)
    agg_both<<<dim3(32, 4, 2), 256, SMEM_AGG>>>(adj, in_rep, out_rep, upd16);

    // 4) out = tanh(upd @ W_upd^T + b_upd)
    final16<<<256, 256, SMEM_FINAL>>>(upd16, Wupdh, b_upd, out);
}